// round 15
// baseline (speedup 1.0000x reference)
#include <cuda_runtime.h>
#include <cuda_bf16.h>
#include <math.h>
#include <stdint.h>

#define TT 512
#define BB 64
#define DD 512
#define HH 512
#define GG 2048   // 4H

// ---------------- scratch (static device allocations only) ----------------
__device__ float g_xg[2][TT * BB][GG];          // precomputed x@Wih^T + bias
__device__ __nv_bfloat16 g_hs[2][2][2][BB][HH]; // [buf][dir][hi/lo][b][k]
__device__ unsigned g_bar_count[2];
__device__ volatile unsigned g_bar_gen[2];
__device__ volatile unsigned g_flag[2][64];
__device__ __nv_bfloat16 g_xh[TT * BB * DD];    // x split hi
__device__ __nv_bfloat16 g_xl[TT * BB * DD];    // x split lo
__device__ __nv_bfloat16 g_wh[2][GG * DD];      // Wih split hi (per dir)
__device__ __nv_bfloat16 g_wl[2][GG * DD];      // Wih split lo

// ---------------- PTX helpers (baseline ISA only — no tcgen05!) ------------
__device__ __forceinline__ uint32_t smem_to_u32(const void* p) {
    uint32_t a;
    asm("{ .reg .u64 t; cvta.to.shared.u64 t, %1; cvt.u32.u64 %0, t; }"
        : "=r"(a) : "l"(p));
    return a;
}
__device__ __forceinline__ void cp_async16(uint32_t dst, const void* src) {
    asm volatile("cp.async.cg.shared.global [%0], [%1], 16;" :: "r"(dst), "l"(src));
}
__device__ __forceinline__ void cp_commit() { asm volatile("cp.async.commit_group;"); }
__device__ __forceinline__ void cp_wait0()  { asm volatile("cp.async.wait_group 0;"); }

__device__ __forceinline__ void ldsm_x4(uint32_t* r, uint32_t a) {
    asm volatile("ldmatrix.sync.aligned.m8n8.x4.shared.b16 {%0,%1,%2,%3}, [%4];"
                 : "=r"(r[0]), "=r"(r[1]), "=r"(r[2]), "=r"(r[3]) : "r"(a));
}
__device__ __forceinline__ void ldsm_x2(uint32_t* r, uint32_t a) {
    asm volatile("ldmatrix.sync.aligned.m8n8.x2.shared.b16 {%0,%1}, [%2];"
                 : "=r"(r[0]), "=r"(r[1]) : "r"(a));
}
__device__ __forceinline__ void mma16816(float* c, const uint32_t* a, const uint32_t* b) {
    asm volatile("mma.sync.aligned.m16n8k16.row.col.f32.bf16.bf16.f32 "
                 "{%0,%1,%2,%3}, {%4,%5,%6,%7}, {%8,%9}, {%0,%1,%2,%3};"
                 : "+f"(c[0]), "+f"(c[1]), "+f"(c[2]), "+f"(c[3])
                 : "r"(a[0]), "r"(a[1]), "r"(a[2]), "r"(a[3]), "r"(b[0]), "r"(b[1]));
}

__device__ __forceinline__ float fast_sigmoid(float x) {
    return __fdividef(1.f, 1.f + __expf(-x));
}
__device__ __forceinline__ float fast_tanh(float x) {
    return __fdividef(2.f, 1.f + __expf(-2.f * x)) - 1.f;
}

// ---------------- grid barrier (rec init) -----------------------------------
__device__ __forceinline__ void dir_barrier(int dir, unsigned target) {
    __syncthreads();
    if (threadIdx.x == 0) {
        __threadfence();
        if (atomicAdd(&g_bar_count[dir], 1u) == 63u) {
            g_bar_count[dir] = 0u;
            __threadfence();
            g_bar_gen[dir] = target;
        } else {
            while ((int)(g_bar_gen[dir] - target) < 0) { }
            __threadfence();
        }
    }
    __syncthreads();
}

// ---------------- kernel 0: fp32 -> bf16 hi/lo split -------------------------
__global__ void __launch_bounds__(256)
split_bf16(const float* __restrict__ src, __nv_bfloat16* __restrict__ hi,
           __nv_bfloat16* __restrict__ lo) {
    int i = (blockIdx.x * 256 + threadIdx.x) * 4;
    float4 v = *(const float4*)(src + i);
    __nv_bfloat16 h[4], l[4];
    float f[4] = {v.x, v.y, v.z, v.w};
#pragma unroll
    for (int k = 0; k < 4; k++) {
        h[k] = __float2bfloat16(f[k]);
        l[k] = __float2bfloat16(f[k] - __bfloat162float(h[k]));
    }
    *(uint2*)(hi + i) = *(uint2*)h;
    *(uint2*)(lo + i) = *(uint2*)l;
}

// ---------------- kernel 1: mma.sync bf16-split precompute GEMM (proven) -----
#define KC       32
#define ROW_B    80
#define TILE_PB  (128 * ROW_B)
#define STAGE_PB (4 * TILE_PB)
#define PRE_SMEM (512 + 2 * STAGE_PB)

__global__ void __launch_bounds__(256)
precompute_mma(const float* __restrict__ bih_f, const float* __restrict__ bhh_f,
               const float* __restrict__ bih_r, const float* __restrict__ bhh_r)
{
    extern __shared__ char smem[];
    float* bias_s = (float*)smem;
    const uint32_t tilesBase = smem_to_u32(smem) + 512;

    const int tid  = threadIdx.x;
    const int wid  = tid >> 5;
    const int lane = tid & 31;
    const int dir  = blockIdx.z;
    const int n0   = blockIdx.x * 128;
    const int m0   = blockIdx.y * 128;
    const int m_off = (wid >> 2) * 64;
    const int n_off = (wid & 3) * 32;

    const __nv_bfloat16* wh = g_wh[dir];
    const __nv_bfloat16* wl = g_wl[dir];
    const float* bi = dir ? bih_r : bih_f;
    const float* bh = dir ? bhh_r : bhh_f;
    if (tid < 128) bias_s[tid] = __ldg(bi + n0 + tid) + __ldg(bh + n0 + tid);

    auto load_chunk = [&](int c, int bf) {
        const uint32_t sbase = tilesBase + bf * STAGE_PB;
        const int k0 = c * KC;
#pragma unroll
        for (int j = 0; j < 8; j++) {
            int idx  = j * 256 + tid;
            int tile = idx >> 9;
            int u    = idx & 511;
            int row  = u >> 2, seg = u & 3;
            uint32_t dst = sbase + tile * TILE_PB + row * ROW_B + seg * 16;
            const __nv_bfloat16* src;
            if (tile < 2) {
                int m = m0 + row;
                int asrc = dir ? ((TT - 1 - (m >> 6)) * BB + (m & 63)) : m;
                src = (tile == 0 ? g_xh : g_xl) + (size_t)asrc * DD + k0 + seg * 8;
            } else {
                src = (tile == 2 ? wh : wl) + (size_t)(n0 + row) * DD + k0 + seg * 8;
            }
            cp_async16(dst, src);
        }
        cp_commit();
    };

    const uint32_t aOff = (uint32_t)((m_off + (lane & 15)) * ROW_B + (lane >> 4) * 16);
    const uint32_t bOff = (uint32_t)((n_off + (lane & 7)) * ROW_B + ((lane >> 3) & 1) * 16);

    float acc[4][4][4];
#pragma unroll
    for (int mt = 0; mt < 4; mt++)
#pragma unroll
        for (int nt = 0; nt < 4; nt++)
#pragma unroll
            for (int q = 0; q < 4; q++) acc[mt][nt][q] = 0.f;

    load_chunk(0, 0);

    for (int c = 0; c < 16; c++) {
        cp_wait0();
        __syncthreads();
        if (c < 15) load_chunk(c + 1, (c + 1) & 1);
        const uint32_t stage = tilesBase + (c & 1) * STAGE_PB;

#pragma unroll
        for (int kk = 0; kk < 2; kk++) {
            uint32_t bhf[4][2], blf[4][2];
#pragma unroll
            for (int nt = 0; nt < 4; nt++) {
                ldsm_x2(bhf[nt], stage + 2 * TILE_PB + bOff + nt * 8 * ROW_B + kk * 32);
                ldsm_x2(blf[nt], stage + 3 * TILE_PB + bOff + nt * 8 * ROW_B + kk * 32);
            }
#pragma unroll
            for (int mt = 0; mt < 4; mt++) {
                uint32_t ahf[4], alf[4];
                ldsm_x4(ahf, stage + 0 * TILE_PB + aOff + mt * 16 * ROW_B + kk * 32);
                ldsm_x4(alf, stage + 1 * TILE_PB + aOff + mt * 16 * ROW_B + kk * 32);
#pragma unroll
                for (int nt = 0; nt < 4; nt++) {
                    mma16816(acc[mt][nt], ahf, bhf[nt]);
                    mma16816(acc[mt][nt], ahf, blf[nt]);
                    mma16816(acc[mt][nt], alf, bhf[nt]);
                }
            }
        }
    }

    const int gid = lane >> 2, qid = lane & 3;
#pragma unroll
    for (int mt = 0; mt < 4; mt++) {
#pragma unroll
        for (int nt = 0; nt < 4; nt++) {
            int nl = n_off + nt * 8 + qid * 2;
            int ml0 = m_off + mt * 16 + gid;
            float2 v0 = make_float2(acc[mt][nt][0] + bias_s[nl],
                                    acc[mt][nt][1] + bias_s[nl + 1]);
            float2 v1 = make_float2(acc[mt][nt][2] + bias_s[nl],
                                    acc[mt][nt][3] + bias_s[nl + 1]);
            *(float2*)&g_xg[dir][m0 + ml0][n0 + nl]     = v0;
            *(float2*)&g_xg[dir][m0 + ml0 + 8][n0 + nl] = v1;
        }
    }
}

// ---------------- kernel 2: persistent recurrence, mma.sync, 8 warps ---------
// 128 CTAs (64/dir), 256 thr = 8 warps. Warp tile: m16(batch) x n16(gate) x
// K512. All 4 A-chunks (h hi/lo) issued up-front as 4 cp.async groups,
// drained with wait_group 3/2/1/0. Whh slice resident in smem (hi/lo).
#define W_PITCH  1040                  // 512*2 + 16 pad
#define WH_OFF   0
#define WH_LO    (32 * W_PITCH)        // 33280
#define A_PITCH  272                   // 128*2 + 16 pad
#define CH_HL    (64 * A_PITCH)        // 17408 (one hi or lo plane)
#define CH_SZ    (2 * CH_HL)           // 34816 per chunk
#define AS_OFF   (2 * 32 * W_PITCH)    // 66560
#define GS_OFF   (AS_OFF + 4 * CH_SZ)  // 205824
#define REC_SMEM (GS_OFF + 64 * 36 * 4) // 215040

__global__ void __launch_bounds__(256, 1)
lstm_rec_mma(const float* __restrict__ mask,
             const float* __restrict__ Whh_f,
             const float* __restrict__ Whh_r,
             float* __restrict__ out)
{
    extern __shared__ char smem[];
    const uint32_t sb = smem_to_u32(smem);
    float* Gs = (float*)(smem + GS_OFF);

    const int tid  = threadIdx.x;
    const int warp = tid >> 5;
    const int lane = tid & 31;
    const int cta  = blockIdx.x;
    const int dir  = cta >> 6;
    const int hc0  = (cta & 63) * 8;
    const int u8   = tid & 7;          // pointwise: h unit
    const int b0   = (tid >> 3) & 31;  // pointwise: batch base (0..31)
    const float* Whh = dir ? Whh_r : Whh_f;

    // ---- load + split Whh slice into smem (once) ----
    for (int q = tid; q < 32 * 512; q += 256) {
        int j = q >> 9, k = q & 511;
        int jg = (j >> 3) * 512 + hc0 + (j & 7);
        float w = __ldg(Whh + (size_t)jg * HH + k);
        __nv_bfloat16 hi = __float2bfloat16(w);
        __nv_bfloat16 lo = __float2bfloat16(w - __bfloat162float(hi));
        *(__nv_bfloat16*)(smem + WH_OFF + j * W_PITCH + k * 2) = hi;
        *(__nv_bfloat16*)(smem + WH_LO  + j * W_PITCH + k * 2) = lo;
    }

    // ---- zero own h slices (both buffers, hi+lo) ----
    for (int q = tid; q < 2048; q += 256) {
        int buf = q >> 10, hl = (q >> 9) & 1, b = (q >> 3) & 63, u = q & 7;
        g_hs[buf][dir][hl][b][hc0 + u] = __float2bfloat16(0.f);
    }
    if (tid == 0) g_flag[dir][cta & 63] = 0u;
    const unsigned gen0 = g_bar_gen[dir];
    dir_barrier(dir, gen0 + 1);

    // ldmatrix per-lane offsets: warp tile m = (warp&3)*16, n = (warp>>2)*16
    const uint32_t aOff = (uint32_t)(((warp & 3) * 16 + (lane & 15)) * A_PITCH
                                     + (lane >> 4) * 16);
    const uint32_t bOff = (uint32_t)(((warp >> 2) * 16 + (lane & 7)
                                      + ((lane >> 4) & 1) * 8) * W_PITCH
                                     + ((lane >> 3) & 1) * 16);

    float c_reg[2]  = {0.f, 0.f};
    float h_prev[2] = {0.f, 0.f};

    for (int t = 0; t < TT; t++) {
        const int buf = t & 1;
        const int tt  = dir ? (TT - 1 - t) : t;
        const __nv_bfloat16* hsrc = &g_hs[buf][dir][0][0][0];

        // prefetch xg + mask (DRAM latency hidden under wait+GEMM)
        float xgi[2], xgf[2], xgg[2], xgo[2], mv[2];
#pragma unroll
        for (int i = 0; i < 2; i++) {
            int b = i * 32 + b0;
            const float* xr = &g_xg[dir][(size_t)t * BB + b][0];
            xgi[i] = __ldg(xr + hc0 + u8);
            xgf[i] = __ldg(xr + 512 + hc0 + u8);
            xgg[i] = __ldg(xr + 1024 + hc0 + u8);
            xgo[i] = __ldg(xr + 1536 + hc0 + u8);
            mv[i]  = __ldg(&mask[tt * BB + b]);
        }

        // wait for all h[t] slices
        if (tid < 64) {
            while (g_flag[dir][tid] < (unsigned)t) { }
        }
        __syncthreads();

        // ---- issue ALL 4 A-chunks up-front (4 commit groups) ----
#pragma unroll
        for (int kc = 0; kc < 4; kc++) {
            const uint32_t base = sb + AS_OFF + kc * CH_SZ;
#pragma unroll
            for (int j = 0; j < 8; j++) {
                int idx = j * 256 + tid;
                int hl  = idx >> 10;
                int u   = idx & 1023;
                int row = u >> 4, seg = u & 15;
                cp_async16(base + hl * CH_HL + row * A_PITCH + seg * 16,
                           hsrc + hl * (BB * HH) + row * HH + kc * 128 + seg * 8);
            }
            cp_commit();
        }

        float acc[2][4];   // [ntile][frag]
#pragma unroll
        for (int nt = 0; nt < 2; nt++)
#pragma unroll
            for (int q = 0; q < 4; q++) acc[nt][q] = 0.f;

#pragma unroll
        for (int kc = 0; kc < 4; kc++) {
            if (kc == 0)      asm volatile("cp.async.wait_group 3;");
            else if (kc == 1) asm volatile("cp.async.wait_group 2;");
            else if (kc == 2) asm volatile("cp.async.wait_group 1;");
            else              asm volatile("cp.async.wait_group 0;");
            __syncthreads();
            const uint32_t sA = sb + AS_OFF + kc * CH_SZ;

#pragma unroll
            for (int kk = 0; kk < 8; kk++) {
                uint32_t ah[4], al[4], bh[4], bl[4];
                ldsm_x4(ah, sA + aOff + kk * 32);
                ldsm_x4(al, sA + CH_HL + aOff + kk * 32);
                const uint32_t kb = (uint32_t)(kc * 256 + kk * 32);
                ldsm_x4(bh, sb + WH_OFF + bOff + kb);
                ldsm_x4(bl, sb + WH_LO + bOff + kb);

                mma16816(acc[0], ah, bh);      mma16816(acc[1], ah, bh + 2);
                mma16816(acc[0], ah, bl);      mma16816(acc[1], ah, bl + 2);
                mma16816(acc[0], al, bh);      mma16816(acc[1], al, bh + 2);
            }
        }

        // stage gate results: Gs[b][j], j = gate*8 + u_local
        {
            const int gid = lane >> 2, qid = lane & 3;
            const int m0r = (warp & 3) * 16 + gid;
            const int jb  = (warp >> 2) * 16;
#pragma unroll
            for (int nt = 0; nt < 2; nt++) {
                int j = jb + nt * 8 + qid * 2;
                *(float2*)&Gs[m0r * 36 + j]       = make_float2(acc[nt][0], acc[nt][1]);
                *(float2*)&Gs[(m0r + 8) * 36 + j] = make_float2(acc[nt][2], acc[nt][3]);
            }
        }
        __syncthreads();

        // pointwise: thread owns (u=u8, b in {b0, b0+32})
#pragma unroll
        for (int i = 0; i < 2; i++) {
            int b = i * 32 + b0;
            float iv = fast_sigmoid(xgi[i] + Gs[b * 36 + u8]);
            float fv = fast_sigmoid(xgf[i] + Gs[b * 36 + 8 + u8]);
            float gv = fast_tanh   (xgg[i] + Gs[b * 36 + 16 + u8]);
            float ov = fast_sigmoid(xgo[i] + Gs[b * 36 + 24 + u8]);

            float cn = fv * c_reg[i] + iv * gv;
            float hn = ov * fast_tanh(cn);
            float m  = mv[i];
            cn = m * cn + (1.f - m) * c_reg[i];
            hn = m * hn + (1.f - m) * h_prev[i];
            c_reg[i]  = cn;
            h_prev[i] = hn;

            __nv_bfloat16 hh = __float2bfloat16(hn);
            __nv_bfloat16 hl = __float2bfloat16(hn - __bfloat162float(hh));
            g_hs[buf ^ 1][dir][0][b][hc0 + u8] = hh;
            g_hs[buf ^ 1][dir][1][b][hc0 + u8] = hl;
            out[(size_t)tt * (BB * 2 * HH) + (size_t)b * (2 * HH)
                + (dir << 9) + hc0 + u8] = hn;
        }
        __syncthreads();
        if (tid == 0) {
            __threadfence();
            g_flag[dir][cta & 63] = (unsigned)(t + 1);
        }
    }
}

// ---------------- launch -----------------------------------------------------
extern "C" void kernel_launch(void* const* d_in, const int* in_sizes, int n_in,
                              void* d_out, int out_size) {
    const float* x     = (const float*)d_in[0];
    const float* mask  = (const float*)d_in[1];
    const float* Wih_f = (const float*)d_in[2];
    const float* Whh_f = (const float*)d_in[3];
    const float* bih_f = (const float*)d_in[4];
    const float* bhh_f = (const float*)d_in[5];
    const float* Wih_r = (const float*)d_in[6];
    const float* Whh_r = (const float*)d_in[7];
    const float* bih_r = (const float*)d_in[8];
    const float* bhh_r = (const float*)d_in[9];
    float* out = (float*)d_out;

    __nv_bfloat16 *xh, *xl, *whf, *wlf, *whr, *wlr;
    cudaGetSymbolAddress((void**)&xh,  g_xh);
    cudaGetSymbolAddress((void**)&xl,  g_xl);
    cudaGetSymbolAddress((void**)&whf, g_wh);
    cudaGetSymbolAddress((void**)&wlf, g_wl);
    whr = whf + (size_t)GG * DD;
    wlr = wlf + (size_t)GG * DD;

    split_bf16<<<(TT * BB * DD) / 1024, 256>>>(x, xh, xl);
    split_bf16<<<(GG * DD) / 1024, 256>>>(Wih_f, whf, wlf);
    split_bf16<<<(GG * DD) / 1024, 256>>>(Wih_r, whr, wlr);

    cudaFuncSetAttribute(precompute_mma,
                         cudaFuncAttributeMaxDynamicSharedMemorySize, PRE_SMEM);
    dim3 grid(GG / 128, (TT * BB) / 128, 2);
    precompute_mma<<<grid, 256, PRE_SMEM>>>(bih_f, bhh_f, bih_r, bhh_r);

    cudaFuncSetAttribute(lstm_rec_mma,
                         cudaFuncAttributeMaxDynamicSharedMemorySize, REC_SMEM);
    lstm_rec_mma<<<128, 256, REC_SMEM>>>(mask, Whh_f, Whh_r, out);
}